// round 2
// baseline (speedup 1.0000x reference)
#include <cuda_runtime.h>
#include <cstdint>

// LatentTexture: quantize-then-bilinear-sample two latent textures.
//   hi: 12 ch, 2048x2048, 8-bit quant (qmax=255)
//   lo:  4 ch,  512x512,  4-bit quant (qmax=15)
// out[b, 0:12] = hi channels, out[b, 12:16] = lo channels.  fp32.
//
// Quantization is pointwise, so apply it per fetched texel instead of
// materializing the quantized textures. Bilinear blend is done in the
// integer-level domain (rintf results), scaled by 1/qmax once at the end.

#define NSAMP 131072

__device__ __forceinline__ float qlevel(float x, float qmax) {
    // round(clip(x,0,1)*qmax)  -- nearest-even matches jnp.round
    float xc = fminf(fmaxf(x, 0.0f), 1.0f);
    return rintf(__fmul_rn(xc, qmax));
}

template <int C, int HW>
__device__ __forceinline__ void sample_tex(const float* __restrict__ tex,
                                           float u, float v,
                                           float qmax, float invq,
                                           float* __restrict__ res) {
    // Replicate reference arithmetic ordering exactly (no fma contraction):
    // gx = u*2-1 ; ix = (gx+1)*0.5*(HW-1)
    float gx = __fadd_rn(__fmul_rn(u, 2.0f), -1.0f);
    float gy = __fadd_rn(__fmul_rn(v, 2.0f), -1.0f);
    float ix = __fmul_rn(__fmul_rn(__fadd_rn(gx, 1.0f), 0.5f), (float)(HW - 1));
    float iy = __fmul_rn(__fmul_rn(__fadd_rn(gy, 1.0f), 0.5f), (float)(HW - 1));

    float ix0f = floorf(ix);
    float iy0f = floorf(iy);
    float wx = __fadd_rn(ix, -ix0f);
    float wy = __fadd_rn(iy, -iy0f);

    int ix0 = min(max((int)ix0f, 0), HW - 1);
    int iy0 = min(max((int)iy0f, 0), HW - 1);
    int ix1 = min(ix0 + 1, HW - 1);
    int iy1 = min(iy0 + 1, HW - 1);

    // Bilinear weights
    float w00 = (1.0f - wy) * (1.0f - wx);
    float w01 = (1.0f - wy) * wx;
    float w10 = wy * (1.0f - wx);
    float w11 = wy * wx;

    size_t r0 = (size_t)iy0 * HW;
    size_t r1 = (size_t)iy1 * HW;
    size_t o00 = r0 + ix0, o01 = r0 + ix1;
    size_t o10 = r1 + ix0, o11 = r1 + ix1;

    const size_t plane = (size_t)HW * HW;

#pragma unroll
    for (int c = 0; c < C; ++c) {
        const float* p = tex + (size_t)c * plane;
        float v00 = qlevel(__ldg(p + o00), qmax);
        float v01 = qlevel(__ldg(p + o01), qmax);
        float v10 = qlevel(__ldg(p + o10), qmax);
        float v11 = qlevel(__ldg(p + o11), qmax);
        float acc = v00 * w00 + v01 * w01 + v10 * w10 + v11 * w11;
        res[c] = acc * invq;
    }
}

__global__ void __launch_bounds__(256)
latent_texture_kernel(const float* __restrict__ uv,
                      const float* __restrict__ hi,
                      const float* __restrict__ lo,
                      float* __restrict__ out) {
    int i = blockIdx.x * blockDim.x + threadIdx.x;
    if (i >= NSAMP) return;

    float2 p = __ldg(reinterpret_cast<const float2*>(uv) + i);

    float res[16];
    sample_tex<12, 2048>(hi, p.x, p.y, 255.0f, 1.0f / 255.0f, res);
    sample_tex<4, 512>(lo, p.x, p.y, 15.0f, 1.0f / 15.0f, res + 12);

    float4* o = reinterpret_cast<float4*>(out + (size_t)i * 16);
    o[0] = make_float4(res[0], res[1], res[2], res[3]);
    o[1] = make_float4(res[4], res[5], res[6], res[7]);
    o[2] = make_float4(res[8], res[9], res[10], res[11]);
    o[3] = make_float4(res[12], res[13], res[14], res[15]);
}

extern "C" void kernel_launch(void* const* d_in, const int* in_sizes, int n_in,
                              void* d_out, int out_size) {
    const float* uv = (const float*)d_in[0];
    const float* hi = (const float*)d_in[1];
    const float* lo = (const float*)d_in[2];
    float* out = (float*)d_out;

    dim3 block(256);
    dim3 grid((NSAMP + 255) / 256);
    latent_texture_kernel<<<grid, block>>>(uv, hi, lo, out);
}

// round 3
// speedup vs baseline: 1.0110x; 1.0110x over previous
#include <cuda_runtime.h>
#include <cstdint>

// LatentTexture: quantize-then-bilinear-sample two latent textures.
//   hi: 12 ch, 2048x2048, 8-bit quant (qmax=255)
//   lo:  4 ch,  512x512,  4-bit quant (qmax=15)
// out[b, 0:12] = hi channels, out[b, 12:16] = lo channels.  fp32.
//
// R2: 4 threads per sample (one per float4 of the 16-float output row).
//   j=0,1,2 -> hi channels 4j..4j+3 ; j=3 -> lo channels 0..3.
// Doubles-ish effective concurrency (524288 threads) and quarters the
// per-thread load chain, to convert the latency-bound 53% DRAM into
// bandwidth-bound. uv is loaded once per quad, shuffled to the other 3 lanes.

#define NSAMP 131072

__device__ __forceinline__ float qlevel(float x, float qmax) {
    float xc = fminf(fmaxf(x, 0.0f), 1.0f);
    return rintf(__fmul_rn(xc, qmax));
}

// Sample 4 consecutive channel planes of a HWxHW texture at (u,v).
template <int HW>
__device__ __forceinline__ void sample4(const float* __restrict__ tex,
                                        float u, float v,
                                        float qmax, float invq,
                                        float* __restrict__ res) {
    // Exact reference arithmetic ordering (no fma contraction):
    float gx = __fadd_rn(__fmul_rn(u, 2.0f), -1.0f);
    float gy = __fadd_rn(__fmul_rn(v, 2.0f), -1.0f);
    float ix = __fmul_rn(__fmul_rn(__fadd_rn(gx, 1.0f), 0.5f), (float)(HW - 1));
    float iy = __fmul_rn(__fmul_rn(__fadd_rn(gy, 1.0f), 0.5f), (float)(HW - 1));

    float ix0f = floorf(ix);
    float iy0f = floorf(iy);
    float wx = __fadd_rn(ix, -ix0f);
    float wy = __fadd_rn(iy, -iy0f);

    int ix0 = min(max((int)ix0f, 0), HW - 1);
    int iy0 = min(max((int)iy0f, 0), HW - 1);
    int ix1 = min(ix0 + 1, HW - 1);
    int iy1 = min(iy0 + 1, HW - 1);

    float w00 = (1.0f - wy) * (1.0f - wx);
    float w01 = (1.0f - wy) * wx;
    float w10 = wy * (1.0f - wx);
    float w11 = wy * wx;

    size_t r0 = (size_t)iy0 * HW;
    size_t r1 = (size_t)iy1 * HW;
    size_t o00 = r0 + ix0, o01 = r0 + ix1;
    size_t o10 = r1 + ix0, o11 = r1 + ix1;

    const size_t plane = (size_t)HW * HW;

    // Issue all 16 loads up front for max MLP, then reduce.
    float t00[4], t01[4], t10[4], t11[4];
#pragma unroll
    for (int c = 0; c < 4; ++c) {
        const float* p = tex + (size_t)c * plane;
        t00[c] = __ldg(p + o00);
        t01[c] = __ldg(p + o01);
        t10[c] = __ldg(p + o10);
        t11[c] = __ldg(p + o11);
    }
#pragma unroll
    for (int c = 0; c < 4; ++c) {
        float acc = qlevel(t00[c], qmax) * w00
                  + qlevel(t01[c], qmax) * w01
                  + qlevel(t10[c], qmax) * w10
                  + qlevel(t11[c], qmax) * w11;
        res[c] = acc * invq;
    }
}

__global__ void __launch_bounds__(256)
latent_texture_kernel(const float* __restrict__ uv,
                      const float* __restrict__ hi,
                      const float* __restrict__ lo,
                      float* __restrict__ out) {
    int t = blockIdx.x * blockDim.x + threadIdx.x;
    int i = t >> 2;       // sample index
    int j = t & 3;        // output float4 group
    if (i >= NSAMP) return;

    int lane = threadIdx.x & 31;
    float u = 0.0f, v = 0.0f;
    if ((lane & 3) == 0) {
        float2 p = __ldg(reinterpret_cast<const float2*>(uv) + i);
        u = p.x;
        v = p.y;
    }
    u = __shfl_sync(0xffffffffu, u, lane & ~3);
    v = __shfl_sync(0xffffffffu, v, lane & ~3);

    float res[4];
    if (j < 3) {
        const size_t plane = (size_t)2048 * 2048;
        sample4<2048>(hi + (size_t)(j * 4) * plane, u, v,
                      255.0f, 1.0f / 255.0f, res);
    } else {
        sample4<512>(lo, u, v, 15.0f, 1.0f / 15.0f, res);
    }

    reinterpret_cast<float4*>(out)[(size_t)i * 4 + j] =
        make_float4(res[0], res[1], res[2], res[3]);
}

extern "C" void kernel_launch(void* const* d_in, const int* in_sizes, int n_in,
                              void* d_out, int out_size) {
    const float* uv = (const float*)d_in[0];
    const float* hi = (const float*)d_in[1];
    const float* lo = (const float*)d_in[2];
    float* out = (float*)d_out;

    int nthreads = NSAMP * 4;
    dim3 block(256);
    dim3 grid((nthreads + 255) / 256);
    latent_texture_kernel<<<grid, block>>>(uv, hi, lo, out);
}

// round 4
// speedup vs baseline: 1.1379x; 1.1255x over previous
#include <cuda_runtime.h>
#include <cstdint>

// LatentTexture: quantize-then-bilinear-sample two latent textures.
//   hi: 12 ch, 2048x2048, 8-bit quant (qmax=255)
//   lo:  4 ch,  512x512,  4-bit quant (qmax=15)
// out[b, 0:12] = hi, out[b, 12:16] = lo.  fp32.
//
// R4: channel-PHASED grid. Phase p (slow grid axis) processes ALL samples for
// one 4-channel group (p=0,1,2 -> hi ch 4p..4p+3, p=3 -> lo). Per-channel
// touched-granule working set is ~10.5 MB, so with ~2 phases resident the L2
// (126 MB) captures cross-sample granule reuse that a fully interleaved
// schedule thrashes away (~37% of gather fetches are repeats).

#define NSAMP 131072
#define BLK 256
#define BLOCKS_PER_PHASE (NSAMP / BLK)   // 512

__device__ __forceinline__ float qlevel(float x, float qmax) {
    float xc = fminf(fmaxf(x, 0.0f), 1.0f);
    return rintf(__fmul_rn(xc, qmax));
}

// Sample 4 consecutive channel planes of a HWxHW texture at (u,v).
template <int HW>
__device__ __forceinline__ void sample4(const float* __restrict__ tex,
                                        float u, float v,
                                        float qmax, float invq,
                                        float* __restrict__ res) {
    // Exact reference arithmetic ordering (no fma contraction):
    float gx = __fadd_rn(__fmul_rn(u, 2.0f), -1.0f);
    float gy = __fadd_rn(__fmul_rn(v, 2.0f), -1.0f);
    float ix = __fmul_rn(__fmul_rn(__fadd_rn(gx, 1.0f), 0.5f), (float)(HW - 1));
    float iy = __fmul_rn(__fmul_rn(__fadd_rn(gy, 1.0f), 0.5f), (float)(HW - 1));

    float ix0f = floorf(ix);
    float iy0f = floorf(iy);
    float wx = __fadd_rn(ix, -ix0f);
    float wy = __fadd_rn(iy, -iy0f);

    int ix0 = min(max((int)ix0f, 0), HW - 1);
    int iy0 = min(max((int)iy0f, 0), HW - 1);
    int ix1 = min(ix0 + 1, HW - 1);
    int iy1 = min(iy0 + 1, HW - 1);

    float w00 = (1.0f - wy) * (1.0f - wx);
    float w01 = (1.0f - wy) * wx;
    float w10 = wy * (1.0f - wx);
    float w11 = wy * wx;

    size_t r0 = (size_t)iy0 * HW;
    size_t r1 = (size_t)iy1 * HW;
    size_t o00 = r0 + ix0, o01 = r0 + ix1;
    size_t o10 = r1 + ix0, o11 = r1 + ix1;

    const size_t plane = (size_t)HW * HW;

    // Issue all 16 loads up front for max MLP, then reduce.
    float t00[4], t01[4], t10[4], t11[4];
#pragma unroll
    for (int c = 0; c < 4; ++c) {
        const float* p = tex + (size_t)c * plane;
        t00[c] = __ldg(p + o00);
        t01[c] = __ldg(p + o01);
        t10[c] = __ldg(p + o10);
        t11[c] = __ldg(p + o11);
    }
#pragma unroll
    for (int c = 0; c < 4; ++c) {
        float acc = qlevel(t00[c], qmax) * w00
                  + qlevel(t01[c], qmax) * w01
                  + qlevel(t10[c], qmax) * w10
                  + qlevel(t11[c], qmax) * w11;
        res[c] = acc * invq;
    }
}

__global__ void __launch_bounds__(BLK)
latent_texture_kernel(const float* __restrict__ uv,
                      const float* __restrict__ hi,
                      const float* __restrict__ lo,
                      float* __restrict__ out) {
    int p = blockIdx.x / BLOCKS_PER_PHASE;              // channel-group phase
    int i = (blockIdx.x % BLOCKS_PER_PHASE) * BLK + threadIdx.x;  // sample

    float2 pos = __ldg(reinterpret_cast<const float2*>(uv) + i);

    float res[4];
    if (p < 3) {
        const size_t plane = (size_t)2048 * 2048;
        sample4<2048>(hi + (size_t)(p * 4) * plane, pos.x, pos.y,
                      255.0f, 1.0f / 255.0f, res);
    } else {
        sample4<512>(lo, pos.x, pos.y, 15.0f, 1.0f / 15.0f, res);
    }

    reinterpret_cast<float4*>(out)[(size_t)i * 4 + p] =
        make_float4(res[0], res[1], res[2], res[3]);
}

extern "C" void kernel_launch(void* const* d_in, const int* in_sizes, int n_in,
                              void* d_out, int out_size) {
    const float* uv = (const float*)d_in[0];
    const float* hi = (const float*)d_in[1];
    const float* lo = (const float*)d_in[2];
    float* out = (float*)d_out;

    dim3 block(BLK);
    dim3 grid(4 * BLOCKS_PER_PHASE);   // 4 phases x 512 blocks
    latent_texture_kernel<<<grid, block>>>(uv, hi, lo, out);
}